// round 14
// baseline (speedup 1.0000x reference)
#include <cuda_runtime.h>
#include <cuda_fp16.h>
#include <cstdint>
#include <math.h>

// ---------------------------------------------------------------------------
// Problem constants
// ---------------------------------------------------------------------------
#define B_    16
#define Hh    56
#define Ww    56
#define Nn    3136
#define C_    384
#define C3    1152
#define HEADS_ 12
#define HD    32
#define WS_   7
#define WT    49
#define WG    8
#define NW    64
#define M_ROWS (B_*Nn)      // 50176

// ---------------------------------------------------------------------------
// Scratch (__device__ globals; no allocations allowed)
// ---------------------------------------------------------------------------
__device__ float g_qkv[(size_t)M_ROWS * C3];   // fp32 q|k|v
__device__ float g_y  [(size_t)M_ROWS * C_];   // attn out + LIM (fp32)
__device__ __half g_wqh[C_ * C3];              // fp16 weights
__device__ __half g_wph[C_ * C_];

// ---------------------------------------------------------------------------
// helpers
// ---------------------------------------------------------------------------
__device__ __forceinline__ uint32_t smem_u32(const void* p) {
    return (uint32_t)__cvta_generic_to_shared(p);
}
__device__ __forceinline__ void ldsm4(uint32_t* r, uint32_t addr) {
    asm volatile("ldmatrix.sync.aligned.m8n8.x4.shared.b16 {%0,%1,%2,%3}, [%4];\n"
                 : "=r"(r[0]), "=r"(r[1]), "=r"(r[2]), "=r"(r[3]) : "r"(addr));
}
__device__ __forceinline__ void ldsm4t(uint32_t* r, uint32_t addr) {
    asm volatile("ldmatrix.sync.aligned.m8n8.x4.trans.shared.b16 {%0,%1,%2,%3}, [%4];\n"
                 : "=r"(r[0]), "=r"(r[1]), "=r"(r[2]), "=r"(r[3]) : "r"(addr));
}
__device__ __forceinline__ void mma_fp16(float* c, const uint32_t* a,
                                         uint32_t b0, uint32_t b1) {
    asm volatile(
        "mma.sync.aligned.m16n8k16.row.col.f32.f16.f16.f32 "
        "{%0,%1,%2,%3}, {%4,%5,%6,%7}, {%8,%9}, {%0,%1,%2,%3};\n"
        : "+f"(c[0]), "+f"(c[1]), "+f"(c[2]), "+f"(c[3])
        : "r"(a[0]), "r"(a[1]), "r"(a[2]), "r"(a[3]), "r"(b0), "r"(b1));
}
__device__ __forceinline__ void cpasync16(uint32_t dst, const void* src) {
    asm volatile("cp.async.cg.shared.global [%0], [%1], 16;" :: "r"(dst), "l"(src));
}
__device__ __forceinline__ void cp_commit() {
    asm volatile("cp.async.commit_group;" ::: "memory");
}
__device__ __forceinline__ void cp_wait0() {
    asm volatile("cp.async.wait_group 0;" ::: "memory");
}

// FMA-pipe exp (no MUFU). rel err ~2.4e-6.
__device__ __forceinline__ float fast_exp(float x) {
    float t = x * 1.4426950408889634f;
    int   ni = __float2int_rn(t);
    float f  = t - (float)ni;
    float p =        1.3333558146428443e-3f;
    p = fmaf(p, f,   9.6181291076284772e-3f);
    p = fmaf(p, f,   5.5504108664821580e-2f);
    p = fmaf(p, f,   2.4022650695910071e-1f);
    p = fmaf(p, f,   6.9314718055994531e-1f);
    p = fmaf(p, f,   1.0f);
    return p * __int_as_float((ni + 127) << 23);
}

// ---------------------------------------------------------------------------
// Weight prep: fp32 -> fp16 (round-to-nearest)
// ---------------------------------------------------------------------------
__global__ __launch_bounds__(256)
void prep_half_kernel(const float* __restrict__ w, __half* __restrict__ hi, int n4)
{
    int i = blockIdx.x * blockDim.x + threadIdx.x;
    if (i >= n4) return;
    float4 v = reinterpret_cast<const float4*>(w)[i];
    union { __half h[4]; uint2 u; } hu;
    hu.h[0] = __float2half_rn(v.x);
    hu.h[1] = __float2half_rn(v.y);
    hu.h[2] = __float2half_rn(v.z);
    hu.h[3] = __float2half_rn(v.w);
    reinterpret_cast<uint2*>(hi)[i] = hu.u;
}

// ---------------------------------------------------------------------------
// 1-term fp16 HMMA GEMM: C[M,N] = round16(A)[M,K] @ Bh[K,N] (+ bias)
// A fp32 -> fp16 in-register during staging. Block tile 128x128x32,
// 512 threads (16 warps, 32x32 warp tiles), double-buffered, cp.async B.
// ---------------------------------------------------------------------------
#define ABUF 10240             // 128x40 halves (bytes)
#define BBUF 8704              // 32x136 halves (bytes)
#define OFF_AHB 0
#define OFF_BHB (2*ABUF)
#define SMEM_G (2*ABUF + 2*BBUF)   // 37888

__global__ __launch_bounds__(512)
void hgemm(const float* __restrict__ A, const __half* __restrict__ Bh16,
           float* __restrict__ C, int M, int N, int K,
           const float* __restrict__ bias)
{
    extern __shared__ char smem[];
    const uint32_t sb = smem_u32(smem);
    const int tid  = threadIdx.x;
    const int lane = tid & 31;
    const int warp = tid >> 5;
    const int wm = (warp >> 2) * 32;
    const int wn = (warp & 3) * 32;
    const int bx = blockIdx.x, by = blockIdx.y;

    const float*  Ag  = A    + (size_t)by * 128 * K;
    const __half* Bgh = Bh16 + (size_t)bx * 128;

    const int ntiles = K / 32;
    float4 ra[2];

    auto issueB = [&](int buf, int k0) {
        int r = tid >> 4, c8 = (tid & 15) * 8;
        uint32_t off = (uint32_t)(r * 136 + c8) * 2;
        cpasync16(sb + OFF_BHB + buf * BBUF + off, Bgh + (size_t)(k0 + r) * N + c8);
        cp_commit();
    };
    auto loadA = [&](int k0) {
#pragma unroll
        for (int i = 0; i < 2; i++) {
            int seg = tid + i * 512;
            int r = seg >> 3, c4 = (seg & 7) * 4;
            ra[i] = *reinterpret_cast<const float4*>(Ag + (size_t)r * K + k0 + c4);
        }
    };
    auto storeA = [&](int buf) {
#pragma unroll
        for (int i = 0; i < 2; i++) {
            int seg = tid + i * 512;
            int r = seg >> 3, c4 = (seg & 7) * 4;
            union { __half h[4]; uint64_t u; } hu;
            hu.h[0] = __float2half_rn(ra[i].x);
            hu.h[1] = __float2half_rn(ra[i].y);
            hu.h[2] = __float2half_rn(ra[i].z);
            hu.h[3] = __float2half_rn(ra[i].w);
            uint32_t off = (uint32_t)(r * 40 + c4) * 2;
            asm volatile("st.shared.b64 [%0], %1;"
                         :: "r"(sb + OFF_AHB + buf * ABUF + off), "l"(hu.u) : "memory");
        }
    };

    float acc[2][4][4];
#pragma unroll
    for (int mt = 0; mt < 2; mt++)
#pragma unroll
        for (int nt = 0; nt < 4; nt++)
#pragma unroll
            for (int j = 0; j < 4; j++) acc[mt][nt][j] = 0.f;

    issueB(0, 0);
    loadA(0);
    storeA(0);
    cp_wait0();
    __syncthreads();

    for (int kt = 0; kt < ntiles; kt++) {
        const int buf = kt & 1;
        const bool more = (kt + 1 < ntiles);
        if (more) { issueB(1 - buf, (kt + 1) * 32); loadA((kt + 1) * 32); }

        const uint32_t ah_b = sb + OFF_AHB + buf * ABUF;
        const uint32_t bh_b = sb + OFF_BHB + buf * BBUF;
#pragma unroll
        for (int ks = 0; ks < 2; ks++) {
            const int kk = ks * 16;
            uint32_t ah[2][4], bh[2][4];
#pragma unroll
            for (int mt = 0; mt < 2; mt++) {
                uint32_t off = (uint32_t)((wm + mt * 16 + (lane & 15)) * 40
                                          + kk + ((lane >> 4) << 3)) * 2;
                ldsm4(ah[mt], ah_b + off);
            }
#pragma unroll
            for (int bt = 0; bt < 2; bt++) {
                uint32_t off = (uint32_t)((kk + (lane & 15)) * 136
                                          + wn + bt * 16 + ((lane >> 4) << 3)) * 2;
                ldsm4t(bh[bt], bh_b + off);
            }
#pragma unroll
            for (int mt = 0; mt < 2; mt++)
#pragma unroll
                for (int nt = 0; nt < 4; nt++) {
                    uint32_t b0 = bh[nt >> 1][(nt & 1) * 2];
                    uint32_t b1 = bh[nt >> 1][(nt & 1) * 2 + 1];
                    mma_fp16(acc[mt][nt], ah[mt], b0, b1);
                }
        }

        if (more) {
            storeA(1 - buf);
            cp_wait0();
            __syncthreads();
        }
    }

#pragma unroll
    for (int mt = 0; mt < 2; mt++) {
        int r0 = by * 128 + wm + mt * 16 + (lane >> 2);
#pragma unroll
        for (int nt = 0; nt < 4; nt++) {
            int c0 = bx * 128 + wn + nt * 8 + (lane & 3) * 2;
            float bb0 = bias ? bias[c0] : 0.f;
            float bb1 = bias ? bias[c0 + 1] : 0.f;
            float2 v0 = {acc[mt][nt][0] + bb0, acc[mt][nt][1] + bb1};
            float2 v1 = {acc[mt][nt][2] + bb0, acc[mt][nt][3] + bb1};
            *reinterpret_cast<float2*>(&C[(size_t)r0 * N + c0]) = v0;
            *reinterpret_cast<float2*>(&C[(size_t)(r0 + 8) * N + c0]) = v1;
        }
    }
}

// ---------------------------------------------------------------------------
// Tensor-core window attention, one warp per (batch, window, head) (R11).
// ---------------------------------------------------------------------------
__global__ __launch_bounds__(32)
void attn_kernel(const float* __restrict__ qkv, float* __restrict__ y)
{
    __shared__ __align__(16) __half sQ[64][40];
    __shared__ __align__(16) __half sKT[32][72];
    __shared__ __align__(16) __half sV[64][40];

    int blk  = blockIdx.x;
    int head = blk % HEADS_;
    int w    = (blk / HEADS_) % NW;
    int b    = blk / (HEADS_ * NW);
    int wy = w / WG, wx = w % WG;
    const int lane = threadIdx.x;

    for (int idx = lane; idx < 15 * 40; idx += 32) {
        sV[49 + idx / 40][idx % 40] = __ushort_as_half(0);
    }

    for (int idx = lane; idx < WT * 8; idx += 32) {
        int j = idx >> 3, d4 = (idx & 7) * 4;
        int n = (wy * WS_ + j / WS_) * Ww + wx * WS_ + (j % WS_);
        const float* base = qkv + ((size_t)b * Nn + n) * C3 + head * HD + d4;
        float4 qv = *reinterpret_cast<const float4*>(base);
        float4 kv = *reinterpret_cast<const float4*>(base + C_);
        float4 vv = *reinterpret_cast<const float4*>(base + 2 * C_);
        __half2 q0 = __floats2half2_rn(qv.x, qv.y), q1 = __floats2half2_rn(qv.z, qv.w);
        __half2 v0 = __floats2half2_rn(vv.x, vv.y), v1 = __floats2half2_rn(vv.z, vv.w);
        *reinterpret_cast<__half2*>(&sQ[j][d4])     = q0;
        *reinterpret_cast<__half2*>(&sQ[j][d4 + 2]) = q1;
        *reinterpret_cast<__half2*>(&sV[j][d4])     = v0;
        *reinterpret_cast<__half2*>(&sV[j][d4 + 2]) = v1;
        sKT[d4 + 0][j] = __float2half_rn(kv.x);
        sKT[d4 + 1][j] = __float2half_rn(kv.y);
        sKT[d4 + 2][j] = __float2half_rn(kv.z);
        sKT[d4 + 3][j] = __float2half_rn(kv.w);
    }
    __syncwarp();

    const float scale = 0.1767766952966369f;
    const int q4 = lane & 3;
    const int r16 = lane & 15;
    const int csel = (lane >> 4) << 3;

#pragma unroll
    for (int mt = 0; mt < 4; mt++) {
        uint32_t aq[2][4];
#pragma unroll
        for (int ks = 0; ks < 2; ks++)
            ldsm4(aq[ks], smem_u32(&sQ[mt * 16 + r16][ks * 16 + csel]));

        float c[7][4];
#pragma unroll
        for (int nt = 0; nt < 7; nt++)
#pragma unroll
            for (int e = 0; e < 4; e++) c[nt][e] = 0.f;

#pragma unroll
        for (int ntg = 0; ntg < 4; ntg++) {
#pragma unroll
            for (int ks = 0; ks < 2; ks++) {
                uint32_t bh[4];
                ldsm4t(bh, smem_u32(&sKT[ks * 16 + r16][ntg * 16 + csel]));
                mma_fp16(c[ntg * 2], aq[ks], bh[0], bh[1]);
                if (ntg < 3) mma_fp16(c[ntg * 2 + 1], aq[ks], bh[2], bh[3]);
            }
        }

        float rs_lo = 0.f, rs_hi = 0.f;
#pragma unroll
        for (int nt = 0; nt < 7; nt++) {
#pragma unroll
            for (int e = 0; e < 4; e++) {
                int col = nt * 8 + q4 * 2 + (e & 1);
                c[nt][e] = (col < WT) ? fast_exp(c[nt][e] * scale) : 0.f;
            }
            rs_lo += c[nt][0] + c[nt][1];
            rs_hi += c[nt][2] + c[nt][3];
        }
        rs_lo += __shfl_xor_sync(0xffffffff, rs_lo, 1);
        rs_lo += __shfl_xor_sync(0xffffffff, rs_lo, 2);
        rs_hi += __shfl_xor_sync(0xffffffff, rs_hi, 1);
        rs_hi += __shfl_xor_sync(0xffffffff, rs_hi, 2);
        float inv_lo = 1.f / rs_lo, inv_hi = 1.f / rs_hi;

        uint32_t pa[4][4];
#pragma unroll
        for (int kt = 0; kt < 4; kt++) {
            int nt0 = kt * 2, nt1 = kt * 2 + 1;
            __half2 h0 = __floats2half2_rn(c[nt0][0], c[nt0][1]);
            __half2 h1 = __floats2half2_rn(c[nt0][2], c[nt0][3]);
            pa[kt][0] = *reinterpret_cast<uint32_t*>(&h0);
            pa[kt][1] = *reinterpret_cast<uint32_t*>(&h1);
            if (nt1 < 7) {
                __half2 h2 = __floats2half2_rn(c[nt1][0], c[nt1][1]);
                __half2 h3 = __floats2half2_rn(c[nt1][2], c[nt1][3]);
                pa[kt][2] = *reinterpret_cast<uint32_t*>(&h2);
                pa[kt][3] = *reinterpret_cast<uint32_t*>(&h3);
            } else {
                pa[kt][2] = pa[kt][3] = 0u;
            }
        }

        float o[4][4];
#pragma unroll
        for (int nt = 0; nt < 4; nt++)
#pragma unroll
            for (int e = 0; e < 4; e++) o[nt][e] = 0.f;

#pragma unroll
        for (int kt = 0; kt < 4; kt++) {
            uint32_t v0[4], v1[4];
            ldsm4t(v0, smem_u32(&sV[kt * 16 + r16][csel]));
            ldsm4t(v1, smem_u32(&sV[kt * 16 + r16][16 + csel]));
            mma_fp16(o[0], pa[kt], v0[0], v0[1]);
            mma_fp16(o[1], pa[kt], v0[2], v0[3]);
            mma_fp16(o[2], pa[kt], v1[0], v1[1]);
            mma_fp16(o[3], pa[kt], v1[2], v1[3]);
        }

        int r = lane >> 2;
        int row_lo = mt * 16 + r, row_hi = row_lo + 8;
        if (row_lo < WT) {
            int n = (wy * WS_ + row_lo / WS_) * Ww + wx * WS_ + (row_lo % WS_);
            float* yp = y + ((size_t)b * Nn + n) * C_ + head * HD + q4 * 2;
#pragma unroll
            for (int nt = 0; nt < 4; nt++) {
                float2 v = {o[nt][0] * inv_lo, o[nt][1] * inv_lo};
                *reinterpret_cast<float2*>(yp + nt * 8) = v;
            }
        }
        if (row_hi < WT) {
            int n = (wy * WS_ + row_hi / WS_) * Ww + wx * WS_ + (row_hi % WS_);
            float* yp = y + ((size_t)b * Nn + n) * C_ + head * HD + q4 * 2;
#pragma unroll
            for (int nt = 0; nt < 4; nt++) {
                float2 v = {o[nt][2] * inv_hi, o[nt][3] * inv_hi};
                *reinterpret_cast<float2*>(yp + nt * 8) = v;
            }
        }
    }
}

// ---------------------------------------------------------------------------
// Depthwise 3x3 conv (SAME), w-strip (R13).
// ---------------------------------------------------------------------------
#define WSTRIP 8
#define NSTRIP (Ww / WSTRIP)   // 7

__global__ __launch_bounds__(256)
void conv_add_kernel(const float* __restrict__ qkv, const float* __restrict__ wconv,
                     const float* __restrict__ bconv, float* __restrict__ y)
{
    const int C4 = C_ / 4;
    long long idx = (long long)blockIdx.x * blockDim.x + threadIdx.x;
    if (idx >= (long long)B_ * Hh * NSTRIP * C4) return;
    int c4 = (int)(idx % C4);
    int ws = (int)((idx / C4) % NSTRIP);
    int h  = (int)((idx / ((long long)C4 * NSTRIP)) % Hh);
    int b  = (int)(idx / ((long long)C4 * NSTRIP * Hh));
    int c  = c4 * 4;
    int w0 = ws * WSTRIP;

    float4 wt[3][3];
#pragma unroll
    for (int ky = 0; ky < 3; ky++)
#pragma unroll
        for (int kx = 0; kx < 3; kx++)
            wt[ky][kx] = *reinterpret_cast<const float4*>(wconv + (ky * 3 + kx) * C_ + c);
    float4 bias = *reinterpret_cast<const float4*>(bconv + c);

    bool rok[3];
    int hy[3];
#pragma unroll
    for (int ky = 0; ky < 3; ky++) {
        hy[ky] = h + ky - 1;
        rok[ky] = (hy[ky] >= 0 && hy[ky] < Hh);
    }

    auto loadv = [&](int ky, int wx) -> float4 {
        if (!rok[ky] || wx < 0 || wx >= Ww) return make_float4(0.f, 0.f, 0.f, 0.f);
        return *reinterpret_cast<const float4*>(
            qkv + ((size_t)b * Nn + hy[ky] * Ww + wx) * C3 + 2 * C_ + c);
    };

    float4 m1[3], z0[3], p1[3];
#pragma unroll
    for (int ky = 0; ky < 3; ky++) {
        m1[ky] = loadv(ky, w0 - 1);
        z0[ky] = loadv(ky, w0);
    }

    float* yp = y + ((size_t)b * Nn + h * Ww + w0) * C_ + c;

#pragma unroll
    for (int s = 0; s < WSTRIP; s++) {
        int wcur = w0 + s;
#pragma unroll
        for (int ky = 0; ky < 3; ky++) p1[ky] = loadv(ky, wcur + 1);

        float4 acc = bias;
#pragma unroll
        for (int ky = 0; ky < 3; ky++) {
            acc.x = fmaf(m1[ky].x, wt[ky][0].x, acc.x);
            acc.y = fmaf(m1[ky].y, wt[ky][0].y, acc.y);
            acc.z = fmaf(m1[ky].z, wt[ky][0].z, acc.z);
            acc.w = fmaf(m1[ky].w, wt[ky][0].w, acc.w);
            acc.x = fmaf(z0[ky].x, wt[ky][1].x, acc.x);
            acc.y = fmaf(z0[ky].y, wt[ky][1].y, acc.y);
            acc.z = fmaf(z0[ky].z, wt[ky][1].z, acc.z);
            acc.w = fmaf(z0[ky].w, wt[ky][1].w, acc.w);
            acc.x = fmaf(p1[ky].x, wt[ky][2].x, acc.x);
            acc.y = fmaf(p1[ky].y, wt[ky][2].y, acc.y);
            acc.z = fmaf(p1[ky].z, wt[ky][2].z, acc.z);
            acc.w = fmaf(p1[ky].w, wt[ky][2].w, acc.w);
        }

        float4* yo = reinterpret_cast<float4*>(yp + (size_t)s * C_);
        float4 old = *yo;
        old.x += acc.x; old.y += acc.y; old.z += acc.z; old.w += acc.w;
        *yo = old;

#pragma unroll
        for (int ky = 0; ky < 3; ky++) { m1[ky] = z0[ky]; z0[ky] = p1[ky]; }
    }
}

// ---------------------------------------------------------------------------
// Launch
// ---------------------------------------------------------------------------
extern "C" void kernel_launch(void* const* d_in, const int* in_sizes, int n_in,
                              void* d_out, int out_size)
{
    const float* x      = (const float*)d_in[0];
    const float* w_qkv  = (const float*)d_in[1];
    const float* w_proj = (const float*)d_in[2];
    const float* b_proj = (const float*)d_in[3];
    const float* w_conv = (const float*)d_in[4];
    const float* b_conv = (const float*)d_in[5];
    float* out = (float*)d_out;

    float *qkv, *y;
    __half *wqh, *wph;
    cudaGetSymbolAddress((void**)&qkv, g_qkv);
    cudaGetSymbolAddress((void**)&y,   g_y);
    cudaGetSymbolAddress((void**)&wqh, g_wqh);
    cudaGetSymbolAddress((void**)&wph, g_wph);

    cudaFuncSetAttribute(hgemm, cudaFuncAttributeMaxDynamicSharedMemorySize, SMEM_G);

    // 0) weight prep (fp32 -> fp16)
    prep_half_kernel<<<(C_ * C3 / 4 + 255) / 256, 256>>>(w_qkv, wqh, C_ * C3 / 4);
    prep_half_kernel<<<(C_ * C_ / 4 + 255) / 256, 256>>>(w_proj, wph, C_ * C_ / 4);

    // 1) QKV GEMM, 1-term fp16: (50176,384) @ (384,1152)
    {
        dim3 grid(C3 / 128, M_ROWS / 128);
        hgemm<<<grid, 512, SMEM_G>>>(x, wqh, qkv, M_ROWS, C3, C_, nullptr);
    }
    // 2) tensor-core window attention -> y
    attn_kernel<<<B_ * NW * HEADS_, 32>>>(qkv, y);
    // 3) depthwise conv (w-strip), += into y
    {
        long long total = (long long)B_ * Hh * NSTRIP * (C_ / 4);
        conv_add_kernel<<<(unsigned)((total + 255) / 256), 256>>>(qkv, w_conv, b_conv, y);
    }
    // 4) proj GEMM, 1-term fp16 (+bias) -> out
    {
        dim3 grid(C_ / 128, M_ROWS / 128);
        hgemm<<<grid, 512, SMEM_G>>>(y, wph, out, M_ROWS, C_, C_, b_proj);
    }
}

// round 15
// speedup vs baseline: 1.1169x; 1.1169x over previous
#include <cuda_runtime.h>
#include <cuda_fp16.h>
#include <cstdint>
#include <math.h>

// ---------------------------------------------------------------------------
// Problem constants
// ---------------------------------------------------------------------------
#define B_    16
#define Hh    56
#define Ww    56
#define Nn    3136
#define C_    384
#define C3    1152
#define HEADS_ 12
#define HD    32
#define WS_   7
#define WT    49
#define WG    8
#define NW    64
#define M_ROWS (B_*Nn)      // 50176

// ---------------------------------------------------------------------------
// Scratch (__device__ globals; no allocations allowed)
// ---------------------------------------------------------------------------
__device__ __half g_qkv[(size_t)M_ROWS * C3];  // fp16 q|k|v (GEMM output)
__device__ float  g_y  [(size_t)M_ROWS * C_];  // attn out + LIM (fp32)
__device__ __half g_wqh[C_ * C3];              // fp16 weights
__device__ __half g_wph[C_ * C_];

// ---------------------------------------------------------------------------
// helpers
// ---------------------------------------------------------------------------
__device__ __forceinline__ uint32_t smem_u32(const void* p) {
    return (uint32_t)__cvta_generic_to_shared(p);
}
__device__ __forceinline__ void ldsm4(uint32_t* r, uint32_t addr) {
    asm volatile("ldmatrix.sync.aligned.m8n8.x4.shared.b16 {%0,%1,%2,%3}, [%4];\n"
                 : "=r"(r[0]), "=r"(r[1]), "=r"(r[2]), "=r"(r[3]) : "r"(addr));
}
__device__ __forceinline__ void ldsm4t(uint32_t* r, uint32_t addr) {
    asm volatile("ldmatrix.sync.aligned.m8n8.x4.trans.shared.b16 {%0,%1,%2,%3}, [%4];\n"
                 : "=r"(r[0]), "=r"(r[1]), "=r"(r[2]), "=r"(r[3]) : "r"(addr));
}
__device__ __forceinline__ void mma_fp16(float* c, const uint32_t* a,
                                         uint32_t b0, uint32_t b1) {
    asm volatile(
        "mma.sync.aligned.m16n8k16.row.col.f32.f16.f16.f32 "
        "{%0,%1,%2,%3}, {%4,%5,%6,%7}, {%8,%9}, {%0,%1,%2,%3};\n"
        : "+f"(c[0]), "+f"(c[1]), "+f"(c[2]), "+f"(c[3])
        : "r"(a[0]), "r"(a[1]), "r"(a[2]), "r"(a[3]), "r"(b0), "r"(b1));
}
__device__ __forceinline__ void cpasync16(uint32_t dst, const void* src) {
    asm volatile("cp.async.cg.shared.global [%0], [%1], 16;" :: "r"(dst), "l"(src));
}
__device__ __forceinline__ void cp_commit() {
    asm volatile("cp.async.commit_group;" ::: "memory");
}
__device__ __forceinline__ void cp_wait0() {
    asm volatile("cp.async.wait_group 0;" ::: "memory");
}

// FMA-pipe exp (no MUFU). rel err ~2.4e-6.
__device__ __forceinline__ float fast_exp(float x) {
    float t = x * 1.4426950408889634f;
    int   ni = __float2int_rn(t);
    float f  = t - (float)ni;
    float p =        1.3333558146428443e-3f;
    p = fmaf(p, f,   9.6181291076284772e-3f);
    p = fmaf(p, f,   5.5504108664821580e-2f);
    p = fmaf(p, f,   2.4022650695910071e-1f);
    p = fmaf(p, f,   6.9314718055994531e-1f);
    p = fmaf(p, f,   1.0f);
    return p * __int_as_float((ni + 127) << 23);
}

// ---------------------------------------------------------------------------
// Weight prep: fp32 -> fp16 (round-to-nearest)
// ---------------------------------------------------------------------------
__global__ __launch_bounds__(256)
void prep_half_kernel(const float* __restrict__ w, __half* __restrict__ hi, int n4)
{
    int i = blockIdx.x * blockDim.x + threadIdx.x;
    if (i >= n4) return;
    float4 v = reinterpret_cast<const float4*>(w)[i];
    union { __half h[4]; uint2 u; } hu;
    hu.h[0] = __float2half_rn(v.x);
    hu.h[1] = __float2half_rn(v.y);
    hu.h[2] = __float2half_rn(v.z);
    hu.h[3] = __float2half_rn(v.w);
    reinterpret_cast<uint2*>(hi)[i] = hu.u;
}

// ---------------------------------------------------------------------------
// fp16 2-term split HMMA GEMM (R13-proven), templated output type.
// C = (Ah+Al)[M,K] @ Bh[K,N] (+ bias); HALF_OUT stores fp16, else fp32.
// ---------------------------------------------------------------------------
#define ABUF 10240
#define BBUF 8704
#define OFF_AHB 0
#define OFF_ALB (2*ABUF)
#define OFF_BHB (4*ABUF)
#define SMEM_G (4*ABUF + 2*BBUF)

template<bool HALF_OUT>
__global__ __launch_bounds__(512)
void hgemm(const float* __restrict__ A, const __half* __restrict__ Bh16,
           void* __restrict__ Cv, int M, int N, int K,
           const float* __restrict__ bias)
{
    extern __shared__ char smem[];
    const uint32_t sb = smem_u32(smem);
    const int tid  = threadIdx.x;
    const int lane = tid & 31;
    const int warp = tid >> 5;
    const int wm = (warp >> 2) * 32;
    const int wn = (warp & 3) * 32;
    const int bx = blockIdx.x, by = blockIdx.y;

    const float*  Ag  = A    + (size_t)by * 128 * K;
    const __half* Bgh = Bh16 + (size_t)bx * 128;

    const int ntiles = K / 32;
    float4 ra[2];

    auto issueB = [&](int buf, int k0) {
        int r = tid >> 4, c8 = (tid & 15) * 8;
        uint32_t off = (uint32_t)(r * 136 + c8) * 2;
        cpasync16(sb + OFF_BHB + buf * BBUF + off, Bgh + (size_t)(k0 + r) * N + c8);
        cp_commit();
    };
    auto loadA = [&](int k0) {
#pragma unroll
        for (int i = 0; i < 2; i++) {
            int seg = tid + i * 512;
            int r = seg >> 3, c4 = (seg & 7) * 4;
            ra[i] = *reinterpret_cast<const float4*>(Ag + (size_t)r * K + k0 + c4);
        }
    };
    auto storeA = [&](int buf) {
#pragma unroll
        for (int i = 0; i < 2; i++) {
            int seg = tid + i * 512;
            int r = seg >> 3, c4 = (seg & 7) * 4;
            union { __half h[4]; uint64_t u; } hu, lu;
            float f[4] = {ra[i].x, ra[i].y, ra[i].z, ra[i].w};
#pragma unroll
            for (int j = 0; j < 4; j++) {
                __half hb = __float2half_rn(f[j]);
                hu.h[j] = hb;
                lu.h[j] = __float2half_rn(f[j] - __half2float(hb));
            }
            uint32_t off = (uint32_t)(r * 40 + c4) * 2;
            asm volatile("st.shared.b64 [%0], %1;"
                         :: "r"(sb + OFF_AHB + buf * ABUF + off), "l"(hu.u) : "memory");
            asm volatile("st.shared.b64 [%0], %1;"
                         :: "r"(sb + OFF_ALB + buf * ABUF + off), "l"(lu.u) : "memory");
        }
    };

    float acc[2][4][4];
#pragma unroll
    for (int mt = 0; mt < 2; mt++)
#pragma unroll
        for (int nt = 0; nt < 4; nt++)
#pragma unroll
            for (int j = 0; j < 4; j++) acc[mt][nt][j] = 0.f;

    issueB(0, 0);
    loadA(0);
    storeA(0);
    cp_wait0();
    __syncthreads();

    for (int kt = 0; kt < ntiles; kt++) {
        const int buf = kt & 1;
        const bool more = (kt + 1 < ntiles);
        if (more) { issueB(1 - buf, (kt + 1) * 32); loadA((kt + 1) * 32); }

        const uint32_t ah_b = sb + OFF_AHB + buf * ABUF;
        const uint32_t al_b = sb + OFF_ALB + buf * ABUF;
        const uint32_t bh_b = sb + OFF_BHB + buf * BBUF;
#pragma unroll
        for (int ks = 0; ks < 2; ks++) {
            const int kk = ks * 16;
            uint32_t ah[2][4], al[2][4], bh[2][4];
#pragma unroll
            for (int mt = 0; mt < 2; mt++) {
                uint32_t off = (uint32_t)((wm + mt * 16 + (lane & 15)) * 40
                                          + kk + ((lane >> 4) << 3)) * 2;
                ldsm4(ah[mt], ah_b + off);
                ldsm4(al[mt], al_b + off);
            }
#pragma unroll
            for (int bt = 0; bt < 2; bt++) {
                uint32_t off = (uint32_t)((kk + (lane & 15)) * 136
                                          + wn + bt * 16 + ((lane >> 4) << 3)) * 2;
                ldsm4t(bh[bt], bh_b + off);
            }
#pragma unroll
            for (int mt = 0; mt < 2; mt++)
#pragma unroll
                for (int nt = 0; nt < 4; nt++) {
                    uint32_t b0 = bh[nt >> 1][(nt & 1) * 2];
                    uint32_t b1 = bh[nt >> 1][(nt & 1) * 2 + 1];
                    mma_fp16(acc[mt][nt], ah[mt], b0, b1);
                    mma_fp16(acc[mt][nt], al[mt], b0, b1);
                }
        }

        if (more) {
            storeA(1 - buf);
            cp_wait0();
            __syncthreads();
        }
    }

#pragma unroll
    for (int mt = 0; mt < 2; mt++) {
        int r0 = by * 128 + wm + mt * 16 + (lane >> 2);
#pragma unroll
        for (int nt = 0; nt < 4; nt++) {
            int c0 = bx * 128 + wn + nt * 8 + (lane & 3) * 2;
            float bb0 = bias ? bias[c0] : 0.f;
            float bb1 = bias ? bias[c0 + 1] : 0.f;
            float v00 = acc[mt][nt][0] + bb0, v01 = acc[mt][nt][1] + bb1;
            float v10 = acc[mt][nt][2] + bb0, v11 = acc[mt][nt][3] + bb1;
            if (HALF_OUT) {
                __half* Ch = (__half*)Cv;
                __half2 h0 = __floats2half2_rn(v00, v01);
                __half2 h1 = __floats2half2_rn(v10, v11);
                *reinterpret_cast<__half2*>(&Ch[(size_t)r0 * N + c0]) = h0;
                *reinterpret_cast<__half2*>(&Ch[(size_t)(r0 + 8) * N + c0]) = h1;
            } else {
                float* Cf = (float*)Cv;
                float2 f0 = {v00, v01}, f1 = {v10, v11};
                *reinterpret_cast<float2*>(&Cf[(size_t)r0 * N + c0]) = f0;
                *reinterpret_cast<float2*>(&Cf[(size_t)(r0 + 8) * N + c0]) = f1;
            }
        }
    }
}

// ---------------------------------------------------------------------------
// Tensor-core window attention, one warp per (batch, window, head).
// qkv now fp16: Q/V staging is a pure copy; K staged transposed.
// ---------------------------------------------------------------------------
__global__ __launch_bounds__(32)
void attn_kernel(const __half* __restrict__ qkv, float* __restrict__ y)
{
    __shared__ __align__(16) __half sQ[64][40];
    __shared__ __align__(16) __half sKT[32][72];
    __shared__ __align__(16) __half sV[64][40];

    int blk  = blockIdx.x;
    int head = blk % HEADS_;
    int w    = (blk / HEADS_) % NW;
    int b    = blk / (HEADS_ * NW);
    int wy = w / WG, wx = w % WG;
    const int lane = threadIdx.x;

    for (int idx = lane; idx < 15 * 40; idx += 32) {
        sV[49 + idx / 40][idx % 40] = __ushort_as_half(0);
    }

    // stage: 49 tokens x 4 chunks of 8 halves
    for (int idx = lane; idx < WT * 4; idx += 32) {
        int j = idx >> 2, d8 = (idx & 3) * 8;
        int n = (wy * WS_ + j / WS_) * Ww + wx * WS_ + (j % WS_);
        const __half* base = qkv + ((size_t)b * Nn + n) * C3 + head * HD + d8;
        uint4 qv = *reinterpret_cast<const uint4*>(base);
        uint4 kv = *reinterpret_cast<const uint4*>(base + C_);
        uint4 vv = *reinterpret_cast<const uint4*>(base + 2 * C_);
        *reinterpret_cast<uint4*>(&sQ[j][d8]) = qv;
        *reinterpret_cast<uint4*>(&sV[j][d8]) = vv;
        const __half* kh = reinterpret_cast<const __half*>(&kv);
#pragma unroll
        for (int i = 0; i < 8; i++) sKT[d8 + i][j] = kh[i];
    }
    __syncwarp();

    const float scale = 0.1767766952966369f;
    const int q4 = lane & 3;
    const int r16 = lane & 15;
    const int csel = (lane >> 4) << 3;

#pragma unroll
    for (int mt = 0; mt < 4; mt++) {
        uint32_t aq[2][4];
#pragma unroll
        for (int ks = 0; ks < 2; ks++)
            ldsm4(aq[ks], smem_u32(&sQ[mt * 16 + r16][ks * 16 + csel]));

        float c[7][4];
#pragma unroll
        for (int nt = 0; nt < 7; nt++)
#pragma unroll
            for (int e = 0; e < 4; e++) c[nt][e] = 0.f;

#pragma unroll
        for (int ntg = 0; ntg < 4; ntg++) {
#pragma unroll
            for (int ks = 0; ks < 2; ks++) {
                uint32_t bh[4];
                ldsm4t(bh, smem_u32(&sKT[ks * 16 + r16][ntg * 16 + csel]));
                mma_fp16(c[ntg * 2], aq[ks], bh[0], bh[1]);
                if (ntg < 3) mma_fp16(c[ntg * 2 + 1], aq[ks], bh[2], bh[3]);
            }
        }

        float rs_lo = 0.f, rs_hi = 0.f;
#pragma unroll
        for (int nt = 0; nt < 7; nt++) {
#pragma unroll
            for (int e = 0; e < 4; e++) {
                int col = nt * 8 + q4 * 2 + (e & 1);
                c[nt][e] = (col < WT) ? fast_exp(c[nt][e] * scale) : 0.f;
            }
            rs_lo += c[nt][0] + c[nt][1];
            rs_hi += c[nt][2] + c[nt][3];
        }
        rs_lo += __shfl_xor_sync(0xffffffff, rs_lo, 1);
        rs_lo += __shfl_xor_sync(0xffffffff, rs_lo, 2);
        rs_hi += __shfl_xor_sync(0xffffffff, rs_hi, 1);
        rs_hi += __shfl_xor_sync(0xffffffff, rs_hi, 2);
        float inv_lo = 1.f / rs_lo, inv_hi = 1.f / rs_hi;

        uint32_t pa[4][4];
#pragma unroll
        for (int kt = 0; kt < 4; kt++) {
            int nt0 = kt * 2, nt1 = kt * 2 + 1;
            __half2 h0 = __floats2half2_rn(c[nt0][0], c[nt0][1]);
            __half2 h1 = __floats2half2_rn(c[nt0][2], c[nt0][3]);
            pa[kt][0] = *reinterpret_cast<uint32_t*>(&h0);
            pa[kt][1] = *reinterpret_cast<uint32_t*>(&h1);
            if (nt1 < 7) {
                __half2 h2 = __floats2half2_rn(c[nt1][0], c[nt1][1]);
                __half2 h3 = __floats2half2_rn(c[nt1][2], c[nt1][3]);
                pa[kt][2] = *reinterpret_cast<uint32_t*>(&h2);
                pa[kt][3] = *reinterpret_cast<uint32_t*>(&h3);
            } else {
                pa[kt][2] = pa[kt][3] = 0u;
            }
        }

        float o[4][4];
#pragma unroll
        for (int nt = 0; nt < 4; nt++)
#pragma unroll
            for (int e = 0; e < 4; e++) o[nt][e] = 0.f;

#pragma unroll
        for (int kt = 0; kt < 4; kt++) {
            uint32_t v0[4], v1[4];
            ldsm4t(v0, smem_u32(&sV[kt * 16 + r16][csel]));
            ldsm4t(v1, smem_u32(&sV[kt * 16 + r16][16 + csel]));
            mma_fp16(o[0], pa[kt], v0[0], v0[1]);
            mma_fp16(o[1], pa[kt], v0[2], v0[3]);
            mma_fp16(o[2], pa[kt], v1[0], v1[1]);
            mma_fp16(o[3], pa[kt], v1[2], v1[3]);
        }

        int r = lane >> 2;
        int row_lo = mt * 16 + r, row_hi = row_lo + 8;
        if (row_lo < WT) {
            int n = (wy * WS_ + row_lo / WS_) * Ww + wx * WS_ + (row_lo % WS_);
            float* yp = y + ((size_t)b * Nn + n) * C_ + head * HD + q4 * 2;
#pragma unroll
            for (int nt = 0; nt < 4; nt++) {
                float2 v = {o[nt][0] * inv_lo, o[nt][1] * inv_lo};
                *reinterpret_cast<float2*>(yp + nt * 8) = v;
            }
        }
        if (row_hi < WT) {
            int n = (wy * WS_ + row_hi / WS_) * Ww + wx * WS_ + (row_hi % WS_);
            float* yp = y + ((size_t)b * Nn + n) * C_ + head * HD + q4 * 2;
#pragma unroll
            for (int nt = 0; nt < 4; nt++) {
                float2 v = {o[nt][2] * inv_hi, o[nt][3] * inv_hi};
                *reinterpret_cast<float2*>(yp + nt * 8) = v;
            }
        }
    }
}

// ---------------------------------------------------------------------------
// Depthwise 3x3 conv (SAME), w-strip; v now fp16.
// ---------------------------------------------------------------------------
#define WSTRIP 8
#define NSTRIP (Ww / WSTRIP)   // 7

__global__ __launch_bounds__(256)
void conv_add_kernel(const __half* __restrict__ qkv, const float* __restrict__ wconv,
                     const float* __restrict__ bconv, float* __restrict__ y)
{
    const int C4 = C_ / 4;
    long long idx = (long long)blockIdx.x * blockDim.x + threadIdx.x;
    if (idx >= (long long)B_ * Hh * NSTRIP * C4) return;
    int c4 = (int)(idx % C4);
    int ws = (int)((idx / C4) % NSTRIP);
    int h  = (int)((idx / ((long long)C4 * NSTRIP)) % Hh);
    int b  = (int)(idx / ((long long)C4 * NSTRIP * Hh));
    int c  = c4 * 4;
    int w0 = ws * WSTRIP;

    float4 wt[3][3];
#pragma unroll
    for (int ky = 0; ky < 3; ky++)
#pragma unroll
        for (int kx = 0; kx < 3; kx++)
            wt[ky][kx] = *reinterpret_cast<const float4*>(wconv + (ky * 3 + kx) * C_ + c);
    float4 bias = *reinterpret_cast<const float4*>(bconv + c);

    bool rok[3];
    int hy[3];
#pragma unroll
    for (int ky = 0; ky < 3; ky++) {
        hy[ky] = h + ky - 1;
        rok[ky] = (hy[ky] >= 0 && hy[ky] < Hh);
    }

    auto loadv = [&](int ky, int wx) -> float4 {
        if (!rok[ky] || wx < 0 || wx >= Ww) return make_float4(0.f, 0.f, 0.f, 0.f);
        const __half2* p = reinterpret_cast<const __half2*>(
            qkv + ((size_t)b * Nn + hy[ky] * Ww + wx) * C3 + 2 * C_ + c);
        float2 a = __half22float2(p[0]);
        float2 d = __half22float2(p[1]);
        return make_float4(a.x, a.y, d.x, d.y);
    };

    float4 m1[3], z0[3], p1[3];
#pragma unroll
    for (int ky = 0; ky < 3; ky++) {
        m1[ky] = loadv(ky, w0 - 1);
        z0[ky] = loadv(ky, w0);
    }

    float* yp = y + ((size_t)b * Nn + h * Ww + w0) * C_ + c;

#pragma unroll
    for (int s = 0; s < WSTRIP; s++) {
        int wcur = w0 + s;
#pragma unroll
        for (int ky = 0; ky < 3; ky++) p1[ky] = loadv(ky, wcur + 1);

        float4 acc = bias;
#pragma unroll
        for (int ky = 0; ky < 3; ky++) {
            acc.x = fmaf(m1[ky].x, wt[ky][0].x, acc.x);
            acc.y = fmaf(m1[ky].y, wt[ky][0].y, acc.y);
            acc.z = fmaf(m1[ky].z, wt[ky][0].z, acc.z);
            acc.w = fmaf(m1[ky].w, wt[ky][0].w, acc.w);
            acc.x = fmaf(z0[ky].x, wt[ky][1].x, acc.x);
            acc.y = fmaf(z0[ky].y, wt[ky][1].y, acc.y);
            acc.z = fmaf(z0[ky].z, wt[ky][1].z, acc.z);
            acc.w = fmaf(z0[ky].w, wt[ky][1].w, acc.w);
            acc.x = fmaf(p1[ky].x, wt[ky][2].x, acc.x);
            acc.y = fmaf(p1[ky].y, wt[ky][2].y, acc.y);
            acc.z = fmaf(p1[ky].z, wt[ky][2].z, acc.z);
            acc.w = fmaf(p1[ky].w, wt[ky][2].w, acc.w);
        }

        float4* yo = reinterpret_cast<float4*>(yp + (size_t)s * C_);
        float4 old = *yo;
        old.x += acc.x; old.y += acc.y; old.z += acc.z; old.w += acc.w;
        *yo = old;

#pragma unroll
        for (int ky = 0; ky < 3; ky++) { m1[ky] = z0[ky]; z0[ky] = p1[ky]; }
    }
}

// ---------------------------------------------------------------------------
// Launch
// ---------------------------------------------------------------------------
extern "C" void kernel_launch(void* const* d_in, const int* in_sizes, int n_in,
                              void* d_out, int out_size)
{
    const float* x      = (const float*)d_in[0];
    const float* w_qkv  = (const float*)d_in[1];
    const float* w_proj = (const float*)d_in[2];
    const float* b_proj = (const float*)d_in[3];
    const float* w_conv = (const float*)d_in[4];
    const float* b_conv = (const float*)d_in[5];
    float* out = (float*)d_out;

    __half *qkv, *wqh, *wph;
    float *y;
    cudaGetSymbolAddress((void**)&qkv, g_qkv);
    cudaGetSymbolAddress((void**)&y,   g_y);
    cudaGetSymbolAddress((void**)&wqh, g_wqh);
    cudaGetSymbolAddress((void**)&wph, g_wph);

    cudaFuncSetAttribute(hgemm<true>,  cudaFuncAttributeMaxDynamicSharedMemorySize, SMEM_G);
    cudaFuncSetAttribute(hgemm<false>, cudaFuncAttributeMaxDynamicSharedMemorySize, SMEM_G);

    // 0) weight prep (fp32 -> fp16)
    prep_half_kernel<<<(C_ * C3 / 4 + 255) / 256, 256>>>(w_qkv, wqh, C_ * C3 / 4);
    prep_half_kernel<<<(C_ * C_ / 4 + 255) / 256, 256>>>(w_proj, wph, C_ * C_ / 4);

    // 1) QKV GEMM, 2-term fp16 split, fp16 output
    {
        dim3 grid(C3 / 128, M_ROWS / 128);
        hgemm<true><<<grid, 512, SMEM_G>>>(x, wqh, qkv, M_ROWS, C3, C_, nullptr);
    }
    // 2) tensor-core window attention -> y (fp32)
    attn_kernel<<<B_ * NW * HEADS_, 32>>>(qkv, y);
    // 3) depthwise conv (w-strip, fp16 v), += into y
    {
        long long total = (long long)B_ * Hh * NSTRIP * (C_ / 4);
        conv_add_kernel<<<(unsigned)((total + 255) / 256), 256>>>(qkv, w_conv, b_conv, y);
    }
    // 4) proj GEMM, 2-term fp16 split, fp32 output (+bias) -> out
    {
        dim3 grid(C_ / 128, M_ROWS / 128);
        hgemm<false><<<grid, 512, SMEM_G>>>(y, wph, out, M_ROWS, C_, C_, b_proj);
    }
}